// round 7
// baseline (speedup 1.0000x reference)
#include <cuda_runtime.h>
#include <cstdint>

// Problem constants
#define B_    16
#define T_    60
#define N_    196
#define C_    512
#define SEGS_ 10
#define TOPK_ 6
#define TOPM_ 12
#define HEADS_ 4
#define HD_   128
#define CLIP_ 6      // T/SEGS
#define FRAMES_ 36   // CLIP*TOPK
#define SCALE_ 0.08838834764831845f  // 1/sqrt(128)

// Output layout (flattened tuple concat):
//   [0, 294912)              audio_top_k        (B, FRAMES, C)
//   [294912, 3833856)        visual_patch_top_m (B, FRAMES, TOPM, C)
//   [3833856, 7372800)       visual_patch_feat  (B, FRAMES*TOPM, C) == same data
#define OUT_AUDIO_ 0
#define OUT_TOPM_  (B_*FRAMES_*C_)                    // 294912
#define OUT_FEAT_  (OUT_TOPM_ + B_*FRAMES_*TOPM_*C_)  // 3833856

// Device scratch (no allocations allowed)
__device__ float g_q[C_];          // q projection of qst_feat[0], (HEADS*HD)
__device__ float g_qW[HEADS_*C_];  // qW[h,c] = sum_d q[h,d]*Wk[h*HD+d, c]
__device__ int   g_pid;

// ---------------------------------------------------------------------------
// K1: q[j] = dot(qst_feat[0,:], Wq[j,:]) + bq[j].   One warp per output j.
// Launch: <<<64, 256>>>  (512 warps total = 512 outputs)
// ---------------------------------------------------------------------------
__global__ void __launch_bounds__(256)
k1_qproj(const float* __restrict__ qst,
         const float* __restrict__ in_proj_w,
         const float* __restrict__ in_proj_b) {
    int gwarp = (blockIdx.x * blockDim.x + threadIdx.x) >> 5;  // 0..511
    int lane  = threadIdx.x & 31;
    const float4* wrow = (const float4*)(in_proj_w + (size_t)gwarp * C_); // Wq row
    const float4* qv   = (const float4*)qst;                              // qst_feat[0]
    float acc = 0.f;
    #pragma unroll 4
    for (int i = lane; i < C_ / 4; i += 32) {
        float4 a = wrow[i];
        float4 b = qv[i];
        acc += a.x * b.x + a.y * b.y + a.z * b.z + a.w * b.w;
    }
    #pragma unroll
    for (int o = 16; o; o >>= 1) acc += __shfl_xor_sync(0xffffffffu, acc, o);
    if (lane == 0) g_q[gwarp] = acc + in_proj_b[gwarp];
}

// ---------------------------------------------------------------------------
// K2: qW[h,c] = sum_{d<HD} q[h*HD+d] * Wk[h*HD+d, c]
// One block per head, 512 threads = one column each; streams Wk rows coalesced.
// Launch: <<<4, 512>>>
// ---------------------------------------------------------------------------
__global__ void __launch_bounds__(512)
k2_qw(const float* __restrict__ in_proj_w) {
    int h = blockIdx.x;
    int t = threadIdx.x;  // column c
    __shared__ float sq[HD_];
    if (t < HD_) sq[t] = g_q[h * HD_ + t];
    __syncthreads();
    const float* Wk = in_proj_w + (size_t)C_ * C_;  // rows C..2C
    const float* base = Wk + (size_t)(h * HD_) * C_ + t;
    float acc = 0.f;
    #pragma unroll 8
    for (int d = 0; d < HD_; d++) {
        acc += sq[d] * base[(size_t)d * C_];
    }
    g_qW[h * C_ + t] = acc;
}

// ---------------------------------------------------------------------------
// K3: scores[h,n] = SCALE * dot(patch_feat[0, frame0, n, :], qW[h,:])
//     softmax over n per head; patch_weights = mean over heads;
//     pid = max index among top-12 weights (stable-argsort tail semantics).
// Single block, 256 threads (8 warps). Warp per patch row, 4 heads per pass.
// ---------------------------------------------------------------------------
__global__ void __launch_bounds__(256)
k3_pid(const float* __restrict__ patch,
       const int* __restrict__ topk) {
    __shared__ float sqW[HEADS_][C_];
    __shared__ float s[HEADS_][N_];
    __shared__ float w[HEADS_][N_];
    __shared__ float pw[N_];

    int tid = threadIdx.x;
    for (int i = tid; i < HEADS_ * C_; i += blockDim.x)
        ((float*)sqW)[i] = g_qW[i];
    __syncthreads();

    int frame0 = topk[0] * CLIP_;  // top_k_index_sort[0,0,0] * CLIP, b=0
    int warp = tid >> 5, lane = tid & 31;

    // scores: each of 8 warps handles patch rows n = warp, warp+8, ...
    for (int n = warp; n < N_; n += 8) {
        const float4* row =
            (const float4*)(patch + (((size_t)frame0 * N_) + n) * C_);
        float a0 = 0.f, a1 = 0.f, a2 = 0.f, a3 = 0.f;
        #pragma unroll 4
        for (int i = lane; i < C_ / 4; i += 32) {
            float4 p  = row[i];
            float4 w0 = ((const float4*)sqW[0])[i];
            float4 w1 = ((const float4*)sqW[1])[i];
            float4 w2 = ((const float4*)sqW[2])[i];
            float4 w3 = ((const float4*)sqW[3])[i];
            a0 += p.x * w0.x + p.y * w0.y + p.z * w0.z + p.w * w0.w;
            a1 += p.x * w1.x + p.y * w1.y + p.z * w1.z + p.w * w1.w;
            a2 += p.x * w2.x + p.y * w2.y + p.z * w2.z + p.w * w2.w;
            a3 += p.x * w3.x + p.y * w3.y + p.z * w3.z + p.w * w3.w;
        }
        #pragma unroll
        for (int o = 16; o; o >>= 1) {
            a0 += __shfl_xor_sync(0xffffffffu, a0, o);
            a1 += __shfl_xor_sync(0xffffffffu, a1, o);
            a2 += __shfl_xor_sync(0xffffffffu, a2, o);
            a3 += __shfl_xor_sync(0xffffffffu, a3, o);
        }
        if (lane == 0) {
            s[0][n] = a0 * SCALE_;
            s[1][n] = a1 * SCALE_;
            s[2][n] = a2 * SCALE_;
            s[3][n] = a3 * SCALE_;
        }
    }
    __syncthreads();

    // softmax per head: warps 0..3
    if (warp < HEADS_) {
        float m = -1e30f;
        for (int n = lane; n < N_; n += 32) m = fmaxf(m, s[warp][n]);
        #pragma unroll
        for (int o = 16; o; o >>= 1) m = fmaxf(m, __shfl_xor_sync(0xffffffffu, m, o));
        float sum = 0.f;
        for (int n = lane; n < N_; n += 32) {
            float e = expf(s[warp][n] - m);
            w[warp][n] = e;
            sum += e;
        }
        #pragma unroll
        for (int o = 16; o; o >>= 1) sum += __shfl_xor_sync(0xffffffffu, sum, o);
        float inv = 1.f / sum;
        for (int n = lane; n < N_; n += 32) w[warp][n] *= inv;
    }
    __syncthreads();

    for (int n = tid; n < N_; n += blockDim.x)
        pw[n] = 0.25f * (w[0][n] + w[1][n] + w[2][n] + w[3][n]);
    __syncthreads();

    // top-12 by weight; ties prefer larger index (matches stable ascending
    // argsort tail); pid = max index among selected.
    if (tid == 0) {
        bool used[N_];
        #pragma unroll 4
        for (int n = 0; n < N_; n++) used[n] = false;
        int pid = -1;
        for (int it = 0; it < TOPM_; it++) {
            int bi = -1;
            float bv = -1e30f;
            for (int n = 0; n < N_; n++) {
                if (used[n]) continue;
                float v = pw[n];
                if (v > bv || (v == bv && n > bi)) { bv = v; bi = n; }
            }
            used[bi] = true;
            if (bi > pid) pid = bi;
        }
        g_pid = pid;
    }
}

// ---------------------------------------------------------------------------
// K4: writes all three outputs. One block per (b, f); 128 threads (float4).
// Launch: <<<576, 128>>>
// ---------------------------------------------------------------------------
__global__ void __launch_bounds__(128)
k4_out(const float* __restrict__ audio,
       const float* __restrict__ patch,
       const int* __restrict__ topk,
       float* __restrict__ out) {
    int bf = blockIdx.x;
    int b = bf / FRAMES_, f = bf % FRAMES_;
    int fk = f / CLIP_, cc = f % CLIP_;
    int seg = topk[b * TOPK_ + fk];   // top_k_index_sort[b,0,fk]
    int frame = seg * CLIP_ + cc;
    int t = threadIdx.x;
    int pid = g_pid;

    float4 a = ((const float4*)(audio + ((size_t)b * T_ + frame) * C_))[t];
    float4 p = ((const float4*)(patch +
                 (((size_t)b * T_ + frame) * N_ + pid) * C_))[t];

    ((float4*)(out + OUT_AUDIO_ + (size_t)bf * C_))[t] = a;

    float4* s1 = (float4*)(out + OUT_TOPM_ + (size_t)bf * TOPM_ * C_);
    float4* s2 = (float4*)(out + OUT_FEAT_ + (size_t)bf * TOPM_ * C_);
    #pragma unroll
    for (int m = 0; m < TOPM_; m++) {
        s1[m * (C_ / 4) + t] = p;
        s2[m * (C_ / 4) + t] = p;
    }
}

// ---------------------------------------------------------------------------
extern "C" void kernel_launch(void* const* d_in, const int* in_sizes, int n_in,
                              void* d_out, int out_size) {
    const float* audio_feat = (const float*)d_in[0];   // (B,T,C)
    const float* patch_feat = (const float*)d_in[1];   // (B,T,N,C)
    const float* qst_feat   = (const float*)d_in[2];   // (B,C)
    const int*   topk       = (const int*)d_in[3];     // (B,1,TOPK)
    const float* in_proj_w  = (const float*)d_in[4];   // (3C,C)
    const float* in_proj_b  = (const float*)d_in[5];   // (3C,)
    float* out = (float*)d_out;

    k1_qproj<<<64, 256>>>(qst_feat, in_proj_w, in_proj_b);
    k2_qw<<<HEADS_, C_>>>(in_proj_w);
    k3_pid<<<1, 256>>>(patch_feat, topk);
    k4_out<<<B_ * FRAMES_, C_ / 4>>>(audio_feat, patch_feat, topk, out);
}

// round 9
// speedup vs baseline: 4.8981x; 4.8981x over previous
#include <cuda_runtime.h>
#include <cstdint>

// Problem constants
#define B_    16
#define T_    60
#define N_    196
#define C_    512
#define SEGS_ 10
#define TOPK_ 6
#define TOPM_ 12
#define HEADS_ 4
#define HD_   128
#define CLIP_ 6      // T/SEGS
#define FRAMES_ 36   // CLIP*TOPK
#define SCALE_ 0.08838834764831845f  // 1/sqrt(128)

// Output layout (flattened tuple concat):
//   [0, 294912)              audio_top_k        (B, FRAMES, C)
//   [294912, 3833856)        visual_patch_top_m (B, FRAMES, TOPM, C)
//   [3833856, 7372800)       visual_patch_feat  (B, FRAMES*TOPM, C) == same data
#define OUT_AUDIO_ 0
#define OUT_TOPM_  (B_*FRAMES_*C_)                    // 294912
#define OUT_FEAT_  (OUT_TOPM_ + B_*FRAMES_*TOPM_*C_)  // 3833856

// Device scratch (no allocations allowed)
__device__ float g_q[C_];              // q projection of qst_feat[0]
__device__ float g_qW[HEADS_*C_];      // qW[h,c] = sum_d q[h*HD+d]*Wk[h*HD+d, c]
__device__ float g_scores[HEADS_][N_]; // pre-softmax scores (scaled)
__device__ int   g_pid;

// ---------------------------------------------------------------------------
// K1: q[j] = dot(qst_feat[0,:], Wq[j,:]) + bq[j].   One warp per output j.
// Launch: <<<64, 256>>>
// ---------------------------------------------------------------------------
__global__ void __launch_bounds__(256)
k1_qproj(const float* __restrict__ qst,
         const float* __restrict__ in_proj_w,
         const float* __restrict__ in_proj_b) {
    int gwarp = (blockIdx.x * blockDim.x + threadIdx.x) >> 5;  // 0..511
    int lane  = threadIdx.x & 31;
    const float4* wrow = (const float4*)(in_proj_w + (size_t)gwarp * C_);
    const float4* qv   = (const float4*)qst;
    float acc = 0.f;
    #pragma unroll 4
    for (int i = lane; i < C_ / 4; i += 32) {
        float4 a = wrow[i];
        float4 b = qv[i];
        acc += a.x * b.x + a.y * b.y + a.z * b.z + a.w * b.w;
    }
    #pragma unroll
    for (int o = 16; o; o >>= 1) acc += __shfl_xor_sync(0xffffffffu, acc, o);
    if (lane == 0) g_q[gwarp] = acc + in_proj_b[gwarp];
}

// ---------------------------------------------------------------------------
// K2: qW[h,c] = sum_{d<HD} q[h*HD+d] * Wk[h*HD+d, c]
// 16 blocks: (head, col-chunk of 128). 128 threads = one column each.
// ---------------------------------------------------------------------------
__global__ void __launch_bounds__(128)
k2_qw(const float* __restrict__ in_proj_w) {
    int h     = blockIdx.x >> 2;          // 0..3
    int chunk = blockIdx.x & 3;           // 0..3
    int t     = threadIdx.x;              // 0..127
    int c     = chunk * 128 + t;
    __shared__ float sq[HD_];
    sq[t] = g_q[h * HD_ + t];
    __syncthreads();
    const float* Wk = in_proj_w + (size_t)C_ * C_;  // rows C..2C
    const float* base = Wk + (size_t)(h * HD_) * C_ + c;
    float acc = 0.f;
    #pragma unroll 8
    for (int d = 0; d < HD_; d++) {
        acc += sq[d] * base[(size_t)d * C_];
    }
    g_qW[h * C_ + c] = acc;
}

// ---------------------------------------------------------------------------
// K3a: scores[h,n] = SCALE * dot(patch[0, frame0, n, :], qW[h,:])
// Grid of N_ blocks, 128 threads (4 warps = 4 heads per block).
// ---------------------------------------------------------------------------
__global__ void __launch_bounds__(128)
k3a_scores(const float* __restrict__ patch,
           const int* __restrict__ topk) {
    int n = blockIdx.x;
    int warp = threadIdx.x >> 5, lane = threadIdx.x & 31;
    int frame0 = topk[0] * CLIP_;  // top_k_index_sort[0,0,0] * CLIP, b=0

    const float4* row =
        (const float4*)(patch + (((size_t)frame0 * N_) + n) * C_);
    const float4* wv = (const float4*)(g_qW + warp * C_);
    float acc = 0.f;
    #pragma unroll 4
    for (int i = lane; i < C_ / 4; i += 32) {
        float4 p = row[i];
        float4 w = wv[i];
        acc += p.x * w.x + p.y * w.y + p.z * w.z + p.w * w.w;
    }
    #pragma unroll
    for (int o = 16; o; o >>= 1) acc += __shfl_xor_sync(0xffffffffu, acc, o);
    if (lane == 0) g_scores[warp][n] = acc * SCALE_;
}

// ---------------------------------------------------------------------------
// K3b: softmax per head over N; pw = mean over heads; warp-parallel top-12
// selection with tie -> larger index; pid = max selected index.
// Single block, 256 threads.
// ---------------------------------------------------------------------------
__global__ void __launch_bounds__(256)
k3b_pid() {
    __shared__ float w[HEADS_][N_];
    __shared__ float pw[N_];

    int tid = threadIdx.x;
    int warp = tid >> 5, lane = tid & 31;

    // softmax per head: warps 0..3
    if (warp < HEADS_) {
        float m = -1e30f;
        for (int n = lane; n < N_; n += 32) m = fmaxf(m, g_scores[warp][n]);
        #pragma unroll
        for (int o = 16; o; o >>= 1) m = fmaxf(m, __shfl_xor_sync(0xffffffffu, m, o));
        float sum = 0.f;
        for (int n = lane; n < N_; n += 32) {
            float e = expf(g_scores[warp][n] - m);
            w[warp][n] = e;
            sum += e;
        }
        #pragma unroll
        for (int o = 16; o; o >>= 1) sum += __shfl_xor_sync(0xffffffffu, sum, o);
        float inv = 1.f / sum;
        for (int n = lane; n < N_; n += 32) w[warp][n] *= inv;
    }
    __syncthreads();

    for (int n = tid; n < N_; n += blockDim.x)
        pw[n] = 0.25f * (w[0][n] + w[1][n] + w[2][n] + w[3][n]);
    __syncthreads();

    // warp 0: 12 iterations of warp-reduced argmax (tie prefers larger index)
    if (warp == 0) {
        int pid = -1;
        for (int it = 0; it < TOPM_; it++) {
            float bv = -1e30f;
            int bi = -1;
            for (int n = lane; n < N_; n += 32) {
                float v = pw[n];
                if (v > bv || (v == bv && n > bi)) { bv = v; bi = n; }
            }
            #pragma unroll
            for (int o = 16; o; o >>= 1) {
                float ov = __shfl_xor_sync(0xffffffffu, bv, o);
                int   oi = __shfl_xor_sync(0xffffffffu, bi, o);
                if (ov > bv || (ov == bv && oi > bi)) { bv = ov; bi = oi; }
            }
            if (lane == 0) pw[bi] = -1e30f;   // remove winner
            __syncwarp();
            if (bi > pid) pid = bi;
        }
        if (lane == 0) g_pid = pid;
    }
}

// ---------------------------------------------------------------------------
// K4: writes all three outputs. 4 blocks per (b,f): block sub handles 3 TOPM
// rows of both replica outputs; sub==0 also writes the audio row.
// Launch: <<<576*4, 128>>>
// ---------------------------------------------------------------------------
__global__ void __launch_bounds__(128)
k4_out(const float* __restrict__ audio,
       const float* __restrict__ patch,
       const int* __restrict__ topk,
       float* __restrict__ out) {
    int bx = blockIdx.x;
    int bf = bx >> 2, sub = bx & 3;
    int b = bf / FRAMES_, f = bf % FRAMES_;
    int fk = f / CLIP_, cc = f % CLIP_;
    int seg = topk[b * TOPK_ + fk];   // top_k_index_sort[b,0,fk]
    int frame = seg * CLIP_ + cc;
    int t = threadIdx.x;
    int pid = g_pid;

    float4 p = ((const float4*)(patch +
                 (((size_t)b * T_ + frame) * N_ + pid) * C_))[t];

    if (sub == 0) {
        float4 a = ((const float4*)(audio + ((size_t)b * T_ + frame) * C_))[t];
        ((float4*)(out + OUT_AUDIO_ + (size_t)bf * C_))[t] = a;
    }

    float4* s1 = (float4*)(out + OUT_TOPM_ + (size_t)bf * TOPM_ * C_);
    float4* s2 = (float4*)(out + OUT_FEAT_ + (size_t)bf * TOPM_ * C_);
    #pragma unroll
    for (int mm = 0; mm < 3; mm++) {
        int m = sub * 3 + mm;
        s1[m * (C_ / 4) + t] = p;
        s2[m * (C_ / 4) + t] = p;
    }
}

// ---------------------------------------------------------------------------
extern "C" void kernel_launch(void* const* d_in, const int* in_sizes, int n_in,
                              void* d_out, int out_size) {
    const float* audio_feat = (const float*)d_in[0];   // (B,T,C)
    const float* patch_feat = (const float*)d_in[1];   // (B,T,N,C)
    const float* qst_feat   = (const float*)d_in[2];   // (B,C)
    const int*   topk       = (const int*)d_in[3];     // (B,1,TOPK)
    const float* in_proj_w  = (const float*)d_in[4];   // (3C,C)
    const float* in_proj_b  = (const float*)d_in[5];   // (3C,)
    float* out = (float*)d_out;

    k1_qproj<<<64, 256>>>(qst_feat, in_proj_w, in_proj_b);
    k2_qw<<<16, 128>>>(in_proj_w);
    k3a_scores<<<N_, 128>>>(patch_feat, topk);
    k3b_pid<<<1, 256>>>();
    k4_out<<<B_ * FRAMES_ * 4, 128>>>(audio_feat, patch_feat, topk, out);
}